// round 13
// baseline (speedup 1.0000x reference)
#include <cuda_runtime.h>
#include <cuda_fp16.h>
#include <math.h>

// Problem constants
constexpr int B_SZ   = 2;
constexpr int T_SEQ  = 2048;
constexpr int DM     = 1024;
constexpr int HEADS  = 16;
constexpr int DK     = 64;
constexpr int WIN    = 512;
constexpr int M_ROWS = B_SZ * T_SEQ;   // 4096

// Scratch (device globals; no runtime allocation). fp16 packs as u32 (half2).
// g_Q  : Q A-frag pack  [bh][qb(128)][kc(4)][lane(32)][4]      (scaled 1/8)
// g_K  : K B-frag pack  [bh][tile(32)][ntp(4)][kc(4)][lane(32)][4]
// g_V  : V B-frag pack  [bh][tile(32)][kc(4)][nbp(4)][lane(32)][4]
// g_XPK: x A-frag pack  [rb(256)][kc(64)][lane(32)][4]
// g_OPK: attn-out A-frag pack, same layout as g_XPK
// g_WPK: Wq,Wk,Wv,Wo B-frag packs [kc(64)][nbp(64)][lane(32)][4] each
__device__ unsigned g_Q  [2 * 1024 * 1024];
__device__ unsigned g_K  [2 * 1024 * 1024];
__device__ unsigned g_V  [2 * 1024 * 1024];
__device__ unsigned g_XPK[2 * 1024 * 1024];
__device__ unsigned g_OPK[2 * 1024 * 1024];
__device__ unsigned g_WPK[4 * 512 * 1024];

namespace {
struct EagerModuleLoad {
    EagerModuleLoad() {
        void* p = nullptr;
        (void)cudaGetSymbolAddress(&p, g_Q);
        (void)cudaGetSymbolAddress(&p, g_WPK);
        (void)cudaGetSymbolAddress(&p, g_XPK);
    }
};
EagerModuleLoad eager_module_load_;
}

// pack two floats into half2 bits: low16 = lo, high16 = hi
__device__ __forceinline__ unsigned f2h2p(float lo, float hi) {
    unsigned r;
    asm("cvt.rn.f16x2.f32 %0, %1, %2;" : "=r"(r) : "f"(hi), "f"(lo));
    return r;
}

__device__ __forceinline__ void mma_f16(float c[4],
    unsigned a0, unsigned a1, unsigned a2, unsigned a3,
    unsigned b0, unsigned b1)
{
    asm volatile(
        "mma.sync.aligned.m16n8k16.row.col.f32.f16.f16.f32 "
        "{%0,%1,%2,%3}, {%4,%5,%6,%7}, {%8,%9}, {%0,%1,%2,%3};\n"
        : "+f"(c[0]), "+f"(c[1]), "+f"(c[2]), "+f"(c[3])
        : "r"(a0), "r"(a1), "r"(a2), "r"(a3), "r"(b0), "r"(b1));
}

__device__ __forceinline__ void cp_async16(void* smem_dst, const void* gmem_src) {
    unsigned saddr = (unsigned)__cvta_generic_to_shared(smem_dst);
    asm volatile("cp.async.cg.shared.global [%0], [%1], 16;\n"
                 :: "r"(saddr), "l"(gmem_src));
}
__device__ __forceinline__ void cp_async_commit() {
    asm volatile("cp.async.commit_group;\n");
}
template <int N>
__device__ __forceinline__ void cp_async_wait() {
    asm volatile("cp.async.wait_group %0;\n" :: "n"(N) : "memory");
}

// ---------------------------------------------------------------------------
// Scatter addresses (word = u32/half2 index unless noted).
// ---------------------------------------------------------------------------
__device__ __forceinline__ size_t qpk16(int r, int c) {
    int b = r >> 11, t = r & 2047;
    int h = c >> 6,  dl = c & 63;
    int qb = t >> 4, r16 = t & 15;
    int gg = r16 & 7, half = r16 >> 3;
    int kc = dl >> 4, w16 = dl & 15;
    int lane = gg * 4 + ((w16 & 7) >> 1);
    int i = (w16 >> 3) * 2 + half;
    return ((((size_t)(b * 16 + h) * 128 + qb) * 4 + kc) * 32 + lane) * 4 + i;
}
__device__ __forceinline__ size_t kpk16(int r, int c) {
    int b = r >> 11, t = r & 2047;
    int h = c >> 6,  dl = c & 63;
    int tile = t >> 6, tk = t & 63;
    int nt = tk >> 3, gg = tk & 7;
    int ntp = nt >> 1, odd = nt & 1;
    int kc = dl >> 4, w16 = dl & 15;
    int lane = gg * 4 + ((w16 & 7) >> 1);
    int i = w16 >> 3;
    return ((((((size_t)(b * 16 + h) * 32 + tile) * 4 + ntp) * 4 + kc) * 32 + lane) * 4)
           + odd * 2 + i;
}
__device__ __forceinline__ size_t vpk16h(int r, int c) {
    int b = r >> 11, t = r & 2047;
    int h = c >> 6,  dl = c & 63;
    int tile = t >> 6, tk = t & 63;
    int kc = tk >> 4, w16 = tk & 15;
    int i = w16 >> 3, tt = (w16 & 7) >> 1, hp = w16 & 1;
    int nb = dl >> 3, gg = dl & 7;
    int nbp = nb >> 1, odd = nb & 1;
    int lane = gg * 4 + tt;
    size_t word = ((((((size_t)(b * 16 + h) * 32 + tile) * 4 + kc) * 4 + nbp) * 32 + lane) * 4)
                  + odd * 2 + i;
    return word * 2 + hp;
}

// ---------------------------------------------------------------------------
// Merged packing kernel (unchanged from R12)
// ---------------------------------------------------------------------------
__global__ __launch_bounds__(256) void pack_all_kernel(
    const float* __restrict__ X,
    const float* __restrict__ Wq, const float* __restrict__ Wk,
    const float* __restrict__ Wv, const float* __restrict__ Wo,
    unsigned* __restrict__ PA, unsigned* __restrict__ PB)
{
    if (blockIdx.y == 0) {
        const int v    = blockIdx.x * 256 + threadIdx.x;
        const int lane = v & 31;
        const int kc   = (v >> 5) & 63;
        const int rb   = v >> 11;
        const int gg   = lane >> 2, t = lane & 3;
        const float* p0 = X + (size_t)(rb * 16 + gg) * DM + kc * 16 + 2 * t;
        float2 x00 = *(const float2*)(p0);
        float2 x10 = *(const float2*)(p0 + 8 * DM);
        float2 x01 = *(const float2*)(p0 + 8);
        float2 x11 = *(const float2*)(p0 + 8 * DM + 8);
        uint4 o;
        o.x = f2h2p(x00.x, x00.y);
        o.y = f2h2p(x10.x, x10.y);
        o.z = f2h2p(x01.x, x01.y);
        o.w = f2h2p(x11.x, x11.y);
        *(uint4*)(PA + (size_t)v * 4) = o;
    } else {
        const int m = blockIdx.x >> 9;
        const float* W = (m == 0) ? Wq : (m == 1) ? Wk : (m == 2) ? Wv : Wo;
        unsigned* Pz = PB + (size_t)m * 524288;
        const int u    = (blockIdx.x & 511) * 256 + threadIdx.x;
        const int lane = u & 31;
        const int nbp  = (u >> 5) & 63;
        const int kc   = u >> 11;
        const int gg   = lane >> 2, t = lane & 3;
        const int r0 = kc * 16 + 2 * t;
        uint4 o;
        {
            const float* c0 = W + (size_t)r0 * DM + (2 * nbp) * 8 + gg;
            o.x = f2h2p(c0[0],        c0[DM]);
            o.y = f2h2p(c0[8 * DM],   c0[9 * DM]);
        }
        {
            const float* c1 = W + (size_t)r0 * DM + (2 * nbp + 1) * 8 + gg;
            o.z = f2h2p(c1[0],        c1[DM]);
            o.w = f2h2p(c1[8 * DM],   c1[9 * DM]);
        }
        *(uint4*)(Pz + (size_t)u * 4) = o;
    }
}

// ---------------------------------------------------------------------------
// Packed FP16 GEMM: C = A @ W + bias. Tile 128x128, BK=64 (4 k8-chunks per
// barrier), 8 warps (64x32), 3-stage cp.async ring in DYNAMIC smem (96KB).
// Same k-accumulation order as BK=32 version -> bit-identical results.
// mode 0: fp32 out; 1: K-pack; 2: Q-pack (x0.125); 3: V-pack.
// ---------------------------------------------------------------------------
constexpr int GEMM_STAGE_W = 8192;                   // A 4096 + B 4096 words
constexpr int GEMM_SMEM_B  = 3 * GEMM_STAGE_W * 4;   // 98304

__device__ __forceinline__ void tgemm16(const unsigned* __restrict__ APK,
                                        const unsigned* __restrict__ BPK,
                                        const float* __restrict__ bias,
                                        void* __restrict__ Cout, int mode)
{
    extern __shared__ __align__(16) unsigned gsm[];
    // stage s: A at gsm + s*8192, B at gsm + s*8192 + 4096

    const int tid  = threadIdx.x;
    const int lane = tid & 31;
    const int warp = tid >> 5;
    const int wm   = warp >> 2;
    const int wn   = warp & 3;
    const int g    = lane >> 2;
    const int tig  = lane & 3;

    float acc[4][4][4];
    #pragma unroll
    for (int mt = 0; mt < 4; mt++)
        #pragma unroll
        for (int nt = 0; nt < 4; nt++)
            #pragma unroll
            for (int i = 0; i < 4; i++) acc[mt][nt][i] = 0.0f;

    const int rb_l = tid >> 5, w32 = tid & 31;   // A staging: 8 rb x 512 words
    const int kc_l = tid >> 6, j   = tid & 63;   // B staging: 4 kc x 1024 words

    // A pack: [rb][kc(64)][lane][4]; rb stride 8192 words, iter (4 kc) = 512.
    const unsigned* Ap = APK + (size_t)(blockIdx.y * 8 + rb_l) * 8192 + w32 * 16;
    // B pack: word = ((kc*64 + nbp)*32 + lane)*4; per kc this block: 1024 words.
    const unsigned* Bp = BPK + ((size_t)kc_l * 64 + blockIdx.x * 8) * 128 + j * 16;

    auto stage_issue = [&](int it, int s) {
        unsigned* As = gsm + s * GEMM_STAGE_W + rb_l * 512 + w32 * 16;
        const unsigned* a = Ap + (size_t)it * 512;
        cp_async16(As,      a);
        cp_async16(As + 4,  a + 4);
        cp_async16(As + 8,  a + 8);
        cp_async16(As + 12, a + 12);
        unsigned* Bs = gsm + s * GEMM_STAGE_W + 4096 + kc_l * 1024 + j * 16;
        const unsigned* bb = Bp + (size_t)it * 32768;
        cp_async16(Bs,      bb);
        cp_async16(Bs + 4,  bb + 4);
        cp_async16(Bs + 8,  bb + 8);
        cp_async16(Bs + 12, bb + 12);
        cp_async_commit();
    };

    const int NITER = 16;   // K=1024 / BK=64
    stage_issue(0, 0);
    stage_issue(1, 1);

    #pragma unroll 1
    for (int it = 0; it < NITER; it++) {
        const int s = it % 3;
        if (it + 1 < NITER) cp_async_wait<1>(); else cp_async_wait<0>();
        __syncthreads();
        if (it + 2 < NITER) stage_issue(it + 2, (it + 2) % 3);

        const unsigned* As = gsm + s * GEMM_STAGE_W;
        const unsigned* Bs = As + 4096;

        #pragma unroll
        for (int ks = 0; ks < 4; ks++) {
            uint4 af[4];
            uint4 b4[2];
            #pragma unroll
            for (int mt = 0; mt < 4; mt++)
                af[mt] = *(const uint4*)&As[(wm * 4 + mt) * 512 + ks * 128 + lane * 4];
            #pragma unroll
            for (int ntp = 0; ntp < 2; ntp++)
                b4[ntp] = *(const uint4*)&Bs[ks * 1024 + (wn * 2 + ntp) * 128 + lane * 4];
            #pragma unroll
            for (int mt = 0; mt < 4; mt++) {
                mma_f16(acc[mt][0], af[mt].x, af[mt].y, af[mt].z, af[mt].w, b4[0].x, b4[0].y);
                mma_f16(acc[mt][1], af[mt].x, af[mt].y, af[mt].z, af[mt].w, b4[0].z, b4[0].w);
                mma_f16(acc[mt][2], af[mt].x, af[mt].y, af[mt].z, af[mt].w, b4[1].x, b4[1].y);
                mma_f16(acc[mt][3], af[mt].x, af[mt].y, af[mt].z, af[mt].w, b4[1].z, b4[1].w);
            }
        }
    }

    #pragma unroll
    for (int mt = 0; mt < 4; mt++) {
        const int row = blockIdx.y * 128 + wm * 64 + mt * 16 + g;
        #pragma unroll
        for (int nt = 0; nt < 4; nt++) {
            const int col = blockIdx.x * 128 + wn * 32 + nt * 8 + 2 * tig;
            const float b0 = bias[col], b1 = bias[col + 1];
            float v00 = acc[mt][nt][0] + b0, v01 = acc[mt][nt][1] + b1;
            float v10 = acc[mt][nt][2] + b0, v11 = acc[mt][nt][3] + b1;
            if (mode == 0) {
                float* C = (float*)Cout;
                *(float2*)(C + (size_t)row * DM + col)       = make_float2(v00, v01);
                *(float2*)(C + (size_t)(row + 8) * DM + col) = make_float2(v10, v11);
            } else if (mode == 2) {
                unsigned* C = (unsigned*)Cout;
                C[qpk16(row,     col)] = f2h2p(v00 * 0.125f, v01 * 0.125f);
                C[qpk16(row + 8, col)] = f2h2p(v10 * 0.125f, v11 * 0.125f);
            } else if (mode == 1) {
                unsigned* C = (unsigned*)Cout;
                C[kpk16(row,     col)] = f2h2p(v00, v01);
                C[kpk16(row + 8, col)] = f2h2p(v10, v11);
            } else {
                __half* Ch = (__half*)Cout;
                Ch[vpk16h(row,     col)]     = __float2half_rn(v00);
                Ch[vpk16h(row,     col + 1)] = __float2half_rn(v01);
                Ch[vpk16h(row + 8, col)]     = __float2half_rn(v10);
                Ch[vpk16h(row + 8, col + 1)] = __float2half_rn(v11);
            }
        }
    }
}

__global__ __launch_bounds__(256) void qkv_gemm_kernel(
    const float* __restrict__ bq, const float* __restrict__ bk,
    const float* __restrict__ bv)
{
    if (blockIdx.z == 0)
        tgemm16(g_XPK, g_WPK,              bq, g_Q, 2);
    else if (blockIdx.z == 1)
        tgemm16(g_XPK, g_WPK + 524288,     bk, g_K, 1);
    else
        tgemm16(g_XPK, g_WPK + 2 * 524288, bv, g_V, 3);
}

__global__ __launch_bounds__(256) void out_gemm_kernel(
    const float* __restrict__ bo, float* __restrict__ out)
{
    tgemm16(g_OPK, g_WPK + 3 * 524288, bo, out, 0);
}

// ---------------------------------------------------------------------------
// FP16 tensor-core flash attention (unchanged from R12)
// ---------------------------------------------------------------------------
constexpr int ATT_STAGE_W  = 4096;                  // K 2048 + V 2048 words
constexpr int ATT_SMEM_B   = 3 * ATT_STAGE_W * 4;   // 49152

__global__ __launch_bounds__(256, 2) void attn_kernel()
{
    extern __shared__ __align__(16) unsigned smp[];

    const int tid  = threadIdx.x;
    const int lane = tid & 31;
    const int w    = tid >> 5;
    const int g    = lane >> 2;
    const int tig  = lane & 3;

    const int bid = blockIdx.x;
    const int qt  = bid & 15;
    const int h   = (bid >> 4) & 15;
    const int b   = bid >> 8;
    const int t0  = qt * 128;
    const int qbase = t0 + w * 16;
    const size_t bh = (size_t)(b * 16 + h);
    const float NINF = __int_as_float(0xff800000u);

    unsigned qf[4][4];
    {
        const unsigned* qp = g_Q + ((bh * 128 + (qbase >> 4)) * 4) * 128 + lane * 4;
        #pragma unroll
        for (int kc = 0; kc < 4; kc++) {
            uint4 t4 = *(const uint4*)(qp + kc * 128);
            qf[kc][0] = t4.x; qf[kc][1] = t4.y; qf[kc][2] = t4.z; qf[kc][3] = t4.w;
        }
    }

    float Oa[8][4];
    #pragma unroll
    for (int nt = 0; nt < 8; nt++)
        #pragma unroll
        for (int i = 0; i < 4; i++) Oa[nt][i] = 0.0f;

    float mA = -1.0e30f, mB = -1.0e30f, lA = 0.0f, lB = 0.0f;
    const int iA = qbase + g;
    const int iB = iA + 8;

    const int lo = (t0 > (WIN - 1)) ? ((t0 - (WIN - 1)) >> 6) : 0;
    const int hi = (t0 + 127) >> 6;

    const unsigned* ktile = g_K + bh * 65536;
    const unsigned* vtile = g_V + bh * 65536;

    auto tile_issue = [&](int ti, int s) {
        unsigned* Ks = smp + s * ATT_STAGE_W;
        unsigned* Vv = Ks + 2048;
        const unsigned* kp = ktile + (size_t)ti * 2048;
        const unsigned* vp = vtile + (size_t)ti * 2048;
        cp_async16(Ks + tid * 8,     kp + tid * 8);
        cp_async16(Ks + tid * 8 + 4, kp + tid * 8 + 4);
        cp_async16(Vv + tid * 8,     vp + tid * 8);
        cp_async16(Vv + tid * 8 + 4, vp + tid * 8 + 4);
        cp_async_commit();
    };

    tile_issue(lo, 0);
    tile_issue(lo + 1, 1);

    #pragma unroll 1
    for (int ti = lo; ti <= hi; ti++) {
        const int idx = ti - lo;
        const int s   = idx % 3;
        const int kbase = ti << 6;

        if (ti < hi) cp_async_wait<1>(); else cp_async_wait<0>();
        __syncthreads();
        if (ti + 2 <= hi) tile_issue(ti + 2, (idx + 2) % 3);

        const bool active = (kbase <= qbase + 15) && (kbase + 63 >= qbase - (WIN - 1));
        if (!active) continue;

        const unsigned* Ks = smp + s * ATT_STAGE_W;
        const unsigned* Vv = Ks + 2048;

        float S[8][4];
        #pragma unroll
        for (int ntp = 0; ntp < 4; ntp++) {
            S[2*ntp][0] = S[2*ntp][1] = S[2*ntp][2] = S[2*ntp][3] = 0.0f;
            S[2*ntp+1][0] = S[2*ntp+1][1] = S[2*ntp+1][2] = S[2*ntp+1][3] = 0.0f;
            const unsigned* kp2 = Ks + ntp * 512 + lane * 4;
            #pragma unroll
            for (int kc = 0; kc < 4; kc++) {
                uint4 bb = *(const uint4*)(kp2 + kc * 128);
                mma_f16(S[2*ntp],   qf[kc][0], qf[kc][1], qf[kc][2], qf[kc][3], bb.x, bb.y);
                mma_f16(S[2*ntp+1], qf[kc][0], qf[kc][1], qf[kc][2], qf[kc][3], bb.z, bb.w);
            }
        }

        const bool full = (kbase + 63 <= qbase) && (kbase >= qbase - (WIN - 16));
        if (!full) {
            #pragma unroll
            for (int nt = 0; nt < 8; nt++) {
                const int j0 = kbase + nt * 8 + 2 * tig;
                const int j1 = j0 + 1;
                if (j0 > iA || j0 < iA - (WIN - 1)) S[nt][0] = NINF;
                if (j1 > iA || j1 < iA - (WIN - 1)) S[nt][1] = NINF;
                if (j0 > iB || j0 < iB - (WIN - 1)) S[nt][2] = NINF;
                if (j1 > iB || j1 < iB - (WIN - 1)) S[nt][3] = NINF;
            }
        }

        float mtA = NINF, mtB = NINF;
        #pragma unroll
        for (int nt = 0; nt < 8; nt++) {
            mtA = fmaxf(mtA, fmaxf(S[nt][0], S[nt][1]));
            mtB = fmaxf(mtB, fmaxf(S[nt][2], S[nt][3]));
        }
        mtA = fmaxf(mtA, __shfl_xor_sync(0xffffffffu, mtA, 1));
        mtA = fmaxf(mtA, __shfl_xor_sync(0xffffffffu, mtA, 2));
        mtB = fmaxf(mtB, __shfl_xor_sync(0xffffffffu, mtB, 1));
        mtB = fmaxf(mtB, __shfl_xor_sync(0xffffffffu, mtB, 2));

        const float mnA = fmaxf(mA, mtA);
        const float mnB = fmaxf(mB, mtB);
        const float corrA = __expf(mA - mnA);
        const float corrB = __expf(mB - mnB);

        float sumA = 0.0f, sumB = 0.0f;
        unsigned PbA[8], PbB[8];
        #pragma unroll
        for (int nt = 0; nt < 8; nt++) {
            float p0 = __expf(S[nt][0] - mnA);
            float p1 = __expf(S[nt][1] - mnA);
            float p2 = __expf(S[nt][2] - mnB);
            float p3 = __expf(S[nt][3] - mnB);
            unsigned ua = f2h2p(p0, p1);
            unsigned ub = f2h2p(p2, p3);
            PbA[nt] = ua; PbB[nt] = ub;
            float2 fa = __half22float2(*reinterpret_cast<__half2*>(&ua));
            float2 fb = __half22float2(*reinterpret_cast<__half2*>(&ub));
            sumA += fa.x + fa.y;
            sumB += fb.x + fb.y;
        }
        sumA += __shfl_xor_sync(0xffffffffu, sumA, 1);
        sumA += __shfl_xor_sync(0xffffffffu, sumA, 2);
        sumB += __shfl_xor_sync(0xffffffffu, sumB, 1);
        sumB += __shfl_xor_sync(0xffffffffu, sumB, 2);

        lA = lA * corrA + sumA;
        lB = lB * corrB + sumB;
        mA = mnA;
        mB = mnB;

        #pragma unroll
        for (int nt = 0; nt < 8; nt++) {
            Oa[nt][0] *= corrA;  Oa[nt][1] *= corrA;
            Oa[nt][2] *= corrB;  Oa[nt][3] *= corrB;
        }

        #pragma unroll
        for (int kc = 0; kc < 4; kc++) {
            const unsigned a0 = PbA[2 * kc];
            const unsigned a1 = PbB[2 * kc];
            const unsigned a2 = PbA[2 * kc + 1];
            const unsigned a3 = PbB[2 * kc + 1];
            const unsigned* vp2 = Vv + kc * 512 + lane * 4;
            #pragma unroll
            for (int nbp = 0; nbp < 4; nbp++) {
                uint4 bb = *(const uint4*)(vp2 + nbp * 128);
                mma_f16(Oa[2*nbp],   a0, a1, a2, a3, bb.x, bb.y);
                mma_f16(Oa[2*nbp+1], a0, a1, a2, a3, bb.z, bb.w);
            }
        }
    }

    {
        const float invA = 1.0f / lA;
        const float invB = 1.0f / lB;
        const int rb_g = b * 128 + qt * 8 + w;
        unsigned* basep = g_OPK + (size_t)rb_g * 8192;
        #pragma unroll
        for (int nt = 0; nt < 8; nt++) {
            const int kc_g = h * 4 + (nt >> 1);
            const size_t idx = ((size_t)kc_g * 32 + (g * 4 + tig)) * 4 + (nt & 1) * 2;
            basep[idx]     = f2h2p(Oa[nt][0] * invA, Oa[nt][1] * invA);
            basep[idx + 1] = f2h2p(Oa[nt][2] * invB, Oa[nt][3] * invB);
        }
    }
}

// ---------------------------------------------------------------------------
extern "C" void kernel_launch(void* const* d_in, const int* in_sizes, int n_in,
                              void* d_out, int out_size)
{
    const float* x  = (const float*)d_in[0];
    const float* Wq = (const float*)d_in[1];
    const float* bq = (const float*)d_in[2];
    const float* Wk = (const float*)d_in[3];
    const float* bk = (const float*)d_in[4];
    const float* Wv = (const float*)d_in[5];
    const float* bv = (const float*)d_in[6];
    const float* Wo = (const float*)d_in[7];
    const float* bo = (const float*)d_in[8];
    float* out = (float*)d_out;

    unsigned *xpk = nullptr, *wpk = nullptr;
    cudaGetSymbolAddress((void**)&xpk, g_XPK);
    cudaGetSymbolAddress((void**)&wpk, g_WPK);

    static bool attr_set = false;
    if (!attr_set) {
        cudaFuncSetAttribute(attn_kernel,
                             cudaFuncAttributeMaxDynamicSharedMemorySize,
                             ATT_SMEM_B);
        cudaFuncSetAttribute(qkv_gemm_kernel,
                             cudaFuncAttributeMaxDynamicSharedMemorySize,
                             GEMM_SMEM_B);
        cudaFuncSetAttribute(out_gemm_kernel,
                             cudaFuncAttributeMaxDynamicSharedMemorySize,
                             GEMM_SMEM_B);
        attr_set = true;
    }

    pack_all_kernel<<<dim3(2048, 2), 256>>>(x, Wq, Wk, Wv, Wo, xpk, wpk);

    dim3 gq(DM / 128, M_ROWS / 128, 3);
    qkv_gemm_kernel<<<gq, 256, GEMM_SMEM_B>>>(bq, bk, bv);

    const int nblk = B_SZ * HEADS * (T_SEQ / 128);  // 512
    attn_kernel<<<nblk, 256, ATT_SMEM_B>>>();

    dim3 go(DM / 128, M_ROWS / 128, 1);
    out_gemm_kernel<<<go, 256, GEMM_SMEM_B>>>(bo, out);
}

// round 14
// speedup vs baseline: 1.1948x; 1.1948x over previous
#include <cuda_runtime.h>
#include <cuda_fp16.h>
#include <math.h>

// Problem constants
constexpr int B_SZ   = 2;
constexpr int T_SEQ  = 2048;
constexpr int DM     = 1024;
constexpr int HEADS  = 16;
constexpr int DK     = 64;
constexpr int WIN    = 512;
constexpr int M_ROWS = B_SZ * T_SEQ;   // 4096

// Scratch (device globals; no runtime allocation). fp16 packs as u32 (half2).
// g_Q  : Q A-frag pack  [bh][qb(128)][kc(4)][lane(32)][4]      (scaled 1/8)
// g_K  : K B-frag pack  [bh][tile(32)][ntp(4)][kc(4)][lane(32)][4]
// g_V  : V B-frag pack  [bh][tile(32)][kc(4)][nbp(4)][lane(32)][4]
// g_XPK: x A-frag pack  [rb(256)][kc(64)][lane(32)][4]
// g_OPK: attn-out A-frag pack, same layout as g_XPK
// g_WPK: Wq,Wk,Wv,Wo B-frag packs [kc(64)][nbp(64)][lane(32)][4] each
__device__ unsigned g_Q  [2 * 1024 * 1024];
__device__ unsigned g_K  [2 * 1024 * 1024];
__device__ unsigned g_V  [2 * 1024 * 1024];
__device__ unsigned g_XPK[2 * 1024 * 1024];
__device__ unsigned g_OPK[2 * 1024 * 1024];
__device__ unsigned g_WPK[4 * 512 * 1024];

namespace {
struct EagerModuleLoad {
    EagerModuleLoad() {
        void* p = nullptr;
        (void)cudaGetSymbolAddress(&p, g_Q);
        (void)cudaGetSymbolAddress(&p, g_WPK);
        (void)cudaGetSymbolAddress(&p, g_XPK);
    }
};
EagerModuleLoad eager_module_load_;
}

// pack two floats into half2 bits: low16 = lo, high16 = hi
__device__ __forceinline__ unsigned f2h2p(float lo, float hi) {
    unsigned r;
    asm("cvt.rn.f16x2.f32 %0, %1, %2;" : "=r"(r) : "f"(hi), "f"(lo));
    return r;
}

__device__ __forceinline__ void mma_f16(float c[4],
    unsigned a0, unsigned a1, unsigned a2, unsigned a3,
    unsigned b0, unsigned b1)
{
    asm volatile(
        "mma.sync.aligned.m16n8k16.row.col.f32.f16.f16.f32 "
        "{%0,%1,%2,%3}, {%4,%5,%6,%7}, {%8,%9}, {%0,%1,%2,%3};\n"
        : "+f"(c[0]), "+f"(c[1]), "+f"(c[2]), "+f"(c[3])
        : "r"(a0), "r"(a1), "r"(a2), "r"(a3), "r"(b0), "r"(b1));
}

__device__ __forceinline__ void cp_async16(void* smem_dst, const void* gmem_src) {
    unsigned saddr = (unsigned)__cvta_generic_to_shared(smem_dst);
    asm volatile("cp.async.cg.shared.global [%0], [%1], 16;\n"
                 :: "r"(saddr), "l"(gmem_src));
}
__device__ __forceinline__ void cp_async_commit() {
    asm volatile("cp.async.commit_group;\n");
}
template <int N>
__device__ __forceinline__ void cp_async_wait() {
    asm volatile("cp.async.wait_group %0;\n" :: "n"(N) : "memory");
}

// ---------------------------------------------------------------------------
// Scatter addresses (word = u32/half2 index unless noted).
// ---------------------------------------------------------------------------
__device__ __forceinline__ size_t qpk16(int r, int c) {
    int b = r >> 11, t = r & 2047;
    int h = c >> 6,  dl = c & 63;
    int qb = t >> 4, r16 = t & 15;
    int gg = r16 & 7, half = r16 >> 3;
    int kc = dl >> 4, w16 = dl & 15;
    int lane = gg * 4 + ((w16 & 7) >> 1);
    int i = (w16 >> 3) * 2 + half;
    return ((((size_t)(b * 16 + h) * 128 + qb) * 4 + kc) * 32 + lane) * 4 + i;
}
__device__ __forceinline__ size_t kpk16(int r, int c) {
    int b = r >> 11, t = r & 2047;
    int h = c >> 6,  dl = c & 63;
    int tile = t >> 6, tk = t & 63;
    int nt = tk >> 3, gg = tk & 7;
    int ntp = nt >> 1, odd = nt & 1;
    int kc = dl >> 4, w16 = dl & 15;
    int lane = gg * 4 + ((w16 & 7) >> 1);
    int i = w16 >> 3;
    return ((((((size_t)(b * 16 + h) * 32 + tile) * 4 + ntp) * 4 + kc) * 32 + lane) * 4)
           + odd * 2 + i;
}
__device__ __forceinline__ size_t vpk16h(int r, int c) {
    int b = r >> 11, t = r & 2047;
    int h = c >> 6,  dl = c & 63;
    int tile = t >> 6, tk = t & 63;
    int kc = tk >> 4, w16 = tk & 15;
    int i = w16 >> 3, tt = (w16 & 7) >> 1, hp = w16 & 1;
    int nb = dl >> 3, gg = dl & 7;
    int nbp = nb >> 1, odd = nb & 1;
    int lane = gg * 4 + tt;
    size_t word = ((((((size_t)(b * 16 + h) * 32 + tile) * 4 + kc) * 4 + nbp) * 32 + lane) * 4)
                  + odd * 2 + i;
    return word * 2 + hp;
}

// ---------------------------------------------------------------------------
// Merged packing kernel (unchanged from R12)
// ---------------------------------------------------------------------------
__global__ __launch_bounds__(256) void pack_all_kernel(
    const float* __restrict__ X,
    const float* __restrict__ Wq, const float* __restrict__ Wk,
    const float* __restrict__ Wv, const float* __restrict__ Wo,
    unsigned* __restrict__ PA, unsigned* __restrict__ PB)
{
    if (blockIdx.y == 0) {
        const int v    = blockIdx.x * 256 + threadIdx.x;
        const int lane = v & 31;
        const int kc   = (v >> 5) & 63;
        const int rb   = v >> 11;
        const int gg   = lane >> 2, t = lane & 3;
        const float* p0 = X + (size_t)(rb * 16 + gg) * DM + kc * 16 + 2 * t;
        float2 x00 = *(const float2*)(p0);
        float2 x10 = *(const float2*)(p0 + 8 * DM);
        float2 x01 = *(const float2*)(p0 + 8);
        float2 x11 = *(const float2*)(p0 + 8 * DM + 8);
        uint4 o;
        o.x = f2h2p(x00.x, x00.y);
        o.y = f2h2p(x10.x, x10.y);
        o.z = f2h2p(x01.x, x01.y);
        o.w = f2h2p(x11.x, x11.y);
        *(uint4*)(PA + (size_t)v * 4) = o;
    } else {
        const int m = blockIdx.x >> 9;
        const float* W = (m == 0) ? Wq : (m == 1) ? Wk : (m == 2) ? Wv : Wo;
        unsigned* Pz = PB + (size_t)m * 524288;
        const int u    = (blockIdx.x & 511) * 256 + threadIdx.x;
        const int lane = u & 31;
        const int nbp  = (u >> 5) & 63;
        const int kc   = u >> 11;
        const int gg   = lane >> 2, t = lane & 3;
        const int r0 = kc * 16 + 2 * t;
        uint4 o;
        {
            const float* c0 = W + (size_t)r0 * DM + (2 * nbp) * 8 + gg;
            o.x = f2h2p(c0[0],        c0[DM]);
            o.y = f2h2p(c0[8 * DM],   c0[9 * DM]);
        }
        {
            const float* c1 = W + (size_t)r0 * DM + (2 * nbp + 1) * 8 + gg;
            o.z = f2h2p(c1[0],        c1[DM]);
            o.w = f2h2p(c1[8 * DM],   c1[9 * DM]);
        }
        *(uint4*)(Pz + (size_t)u * 4) = o;
    }
}

// ---------------------------------------------------------------------------
// Packed FP16 GEMM: C = A @ W + bias. Tile 128x128x32 (R12 config), 8 warps,
// 4-stage cp.async ring with wait_group<2> (deeper prefetch, same 16KB bursts).
// Same k-accumulation order as R12 -> bit-identical results.
// mode 0: fp32 out; 1: K-pack; 2: Q-pack (x0.125); 3: V-pack.
// ---------------------------------------------------------------------------
constexpr int GEMM_STAGE_W = 4096;                   // A 2048 + B 2048 words
constexpr int GEMM_SMEM_B  = 4 * GEMM_STAGE_W * 4;   // 65536

__device__ __forceinline__ void tgemm16(const unsigned* __restrict__ APK,
                                        const unsigned* __restrict__ BPK,
                                        const float* __restrict__ bias,
                                        void* __restrict__ Cout, int mode)
{
    extern __shared__ __align__(16) unsigned gsm[];
    // stage s: A at gsm + s*4096, B at gsm + s*4096 + 2048

    const int tid  = threadIdx.x;
    const int lane = tid & 31;
    const int warp = tid >> 5;
    const int wm   = warp >> 2;
    const int wn   = warp & 3;
    const int g    = lane >> 2;
    const int tig  = lane & 3;

    float acc[4][4][4];
    #pragma unroll
    for (int mt = 0; mt < 4; mt++)
        #pragma unroll
        for (int nt = 0; nt < 4; nt++)
            #pragma unroll
            for (int i = 0; i < 4; i++) acc[mt][nt][i] = 0.0f;

    const int rb_l = tid >> 5, w32 = tid & 31;   // A staging
    const int kc_l = tid >> 7, j   = tid & 127;  // B staging

    const unsigned* Ap = APK + (size_t)(blockIdx.y * 8 + rb_l) * 8192 + w32 * 8;
    const unsigned* Bp = BPK + ((size_t)kc_l * 64 + blockIdx.x * 8) * 128 + j * 8;

    auto stage_issue = [&](int it, int s) {
        unsigned* As = gsm + s * GEMM_STAGE_W;
        const unsigned* a = Ap + (size_t)it * 256;
        cp_async16(&As[rb_l * 256 + w32 * 8],     a);
        cp_async16(&As[rb_l * 256 + w32 * 8 + 4], a + 4);
        unsigned* Bs = gsm + s * GEMM_STAGE_W + 2048;
        const unsigned* bb = Bp + (size_t)it * 16384;
        cp_async16(&Bs[kc_l * 1024 + j * 8],      bb);
        cp_async16(&Bs[kc_l * 1024 + j * 8 + 4],  bb + 4);
        cp_async_commit();
    };

    const int NITER = 32;   // K=1024 / BK=32
    stage_issue(0, 0);
    stage_issue(1, 1);
    stage_issue(2, 2);

    #pragma unroll 1
    for (int it = 0; it < NITER; it++) {
        const int s = it & 3;
        if (it + 2 < NITER)      cp_async_wait<2>();
        else if (it + 1 < NITER) cp_async_wait<1>();
        else                     cp_async_wait<0>();
        __syncthreads();
        if (it + 3 < NITER) stage_issue(it + 3, (it + 3) & 3);

        const unsigned* As = gsm + s * GEMM_STAGE_W;
        const unsigned* Bs = As + 2048;

        #pragma unroll
        for (int ks = 0; ks < 2; ks++) {
            uint4 af[4];
            uint4 b4[2];
            #pragma unroll
            for (int mt = 0; mt < 4; mt++)
                af[mt] = *(const uint4*)&As[(wm * 4 + mt) * 256 + ks * 128 + lane * 4];
            #pragma unroll
            for (int ntp = 0; ntp < 2; ntp++)
                b4[ntp] = *(const uint4*)&Bs[ks * 1024 + (wn * 2 + ntp) * 128 + lane * 4];
            #pragma unroll
            for (int mt = 0; mt < 4; mt++) {
                mma_f16(acc[mt][0], af[mt].x, af[mt].y, af[mt].z, af[mt].w, b4[0].x, b4[0].y);
                mma_f16(acc[mt][1], af[mt].x, af[mt].y, af[mt].z, af[mt].w, b4[0].z, b4[0].w);
                mma_f16(acc[mt][2], af[mt].x, af[mt].y, af[mt].z, af[mt].w, b4[1].x, b4[1].y);
                mma_f16(acc[mt][3], af[mt].x, af[mt].y, af[mt].z, af[mt].w, b4[1].z, b4[1].w);
            }
        }
    }

    #pragma unroll
    for (int mt = 0; mt < 4; mt++) {
        const int row = blockIdx.y * 128 + wm * 64 + mt * 16 + g;
        #pragma unroll
        for (int nt = 0; nt < 4; nt++) {
            const int col = blockIdx.x * 128 + wn * 32 + nt * 8 + 2 * tig;
            const float b0 = bias[col], b1 = bias[col + 1];
            float v00 = acc[mt][nt][0] + b0, v01 = acc[mt][nt][1] + b1;
            float v10 = acc[mt][nt][2] + b0, v11 = acc[mt][nt][3] + b1;
            if (mode == 0) {
                float* C = (float*)Cout;
                *(float2*)(C + (size_t)row * DM + col)       = make_float2(v00, v01);
                *(float2*)(C + (size_t)(row + 8) * DM + col) = make_float2(v10, v11);
            } else if (mode == 2) {
                unsigned* C = (unsigned*)Cout;
                C[qpk16(row,     col)] = f2h2p(v00 * 0.125f, v01 * 0.125f);
                C[qpk16(row + 8, col)] = f2h2p(v10 * 0.125f, v11 * 0.125f);
            } else if (mode == 1) {
                unsigned* C = (unsigned*)Cout;
                C[kpk16(row,     col)] = f2h2p(v00, v01);
                C[kpk16(row + 8, col)] = f2h2p(v10, v11);
            } else {
                __half* Ch = (__half*)Cout;
                Ch[vpk16h(row,     col)]     = __float2half_rn(v00);
                Ch[vpk16h(row,     col + 1)] = __float2half_rn(v01);
                Ch[vpk16h(row + 8, col)]     = __float2half_rn(v10);
                Ch[vpk16h(row + 8, col + 1)] = __float2half_rn(v11);
            }
        }
    }
}

__global__ __launch_bounds__(256) void qkv_gemm_kernel(
    const float* __restrict__ bq, const float* __restrict__ bk,
    const float* __restrict__ bv)
{
    if (blockIdx.z == 0)
        tgemm16(g_XPK, g_WPK,              bq, g_Q, 2);
    else if (blockIdx.z == 1)
        tgemm16(g_XPK, g_WPK + 524288,     bk, g_K, 1);
    else
        tgemm16(g_XPK, g_WPK + 2 * 524288, bv, g_V, 3);
}

__global__ __launch_bounds__(256) void out_gemm_kernel(
    const float* __restrict__ bo, float* __restrict__ out)
{
    tgemm16(g_OPK, g_WPK + 3 * 524288, bo, out, 0);
}

// ---------------------------------------------------------------------------
// FP16 tensor-core flash attention (unchanged from R12)
// ---------------------------------------------------------------------------
constexpr int ATT_STAGE_W  = 4096;                  // K 2048 + V 2048 words
constexpr int ATT_SMEM_B   = 3 * ATT_STAGE_W * 4;   // 49152

__global__ __launch_bounds__(256, 2) void attn_kernel()
{
    extern __shared__ __align__(16) unsigned smp[];

    const int tid  = threadIdx.x;
    const int lane = tid & 31;
    const int w    = tid >> 5;
    const int g    = lane >> 2;
    const int tig  = lane & 3;

    const int bid = blockIdx.x;
    const int qt  = bid & 15;
    const int h   = (bid >> 4) & 15;
    const int b   = bid >> 8;
    const int t0  = qt * 128;
    const int qbase = t0 + w * 16;
    const size_t bh = (size_t)(b * 16 + h);
    const float NINF = __int_as_float(0xff800000u);

    unsigned qf[4][4];
    {
        const unsigned* qp = g_Q + ((bh * 128 + (qbase >> 4)) * 4) * 128 + lane * 4;
        #pragma unroll
        for (int kc = 0; kc < 4; kc++) {
            uint4 t4 = *(const uint4*)(qp + kc * 128);
            qf[kc][0] = t4.x; qf[kc][1] = t4.y; qf[kc][2] = t4.z; qf[kc][3] = t4.w;
        }
    }

    float Oa[8][4];
    #pragma unroll
    for (int nt = 0; nt < 8; nt++)
        #pragma unroll
        for (int i = 0; i < 4; i++) Oa[nt][i] = 0.0f;

    float mA = -1.0e30f, mB = -1.0e30f, lA = 0.0f, lB = 0.0f;
    const int iA = qbase + g;
    const int iB = iA + 8;

    const int lo = (t0 > (WIN - 1)) ? ((t0 - (WIN - 1)) >> 6) : 0;
    const int hi = (t0 + 127) >> 6;

    const unsigned* ktile = g_K + bh * 65536;
    const unsigned* vtile = g_V + bh * 65536;

    auto tile_issue = [&](int ti, int s) {
        unsigned* Ks = smp + s * ATT_STAGE_W;
        unsigned* Vv = Ks + 2048;
        const unsigned* kp = ktile + (size_t)ti * 2048;
        const unsigned* vp = vtile + (size_t)ti * 2048;
        cp_async16(Ks + tid * 8,     kp + tid * 8);
        cp_async16(Ks + tid * 8 + 4, kp + tid * 8 + 4);
        cp_async16(Vv + tid * 8,     vp + tid * 8);
        cp_async16(Vv + tid * 8 + 4, vp + tid * 8 + 4);
        cp_async_commit();
    };

    tile_issue(lo, 0);
    tile_issue(lo + 1, 1);

    #pragma unroll 1
    for (int ti = lo; ti <= hi; ti++) {
        const int idx = ti - lo;
        const int s   = idx % 3;
        const int kbase = ti << 6;

        if (ti < hi) cp_async_wait<1>(); else cp_async_wait<0>();
        __syncthreads();
        if (ti + 2 <= hi) tile_issue(ti + 2, (idx + 2) % 3);

        const bool active = (kbase <= qbase + 15) && (kbase + 63 >= qbase - (WIN - 1));
        if (!active) continue;

        const unsigned* Ks = smp + s * ATT_STAGE_W;
        const unsigned* Vv = Ks + 2048;

        float S[8][4];
        #pragma unroll
        for (int ntp = 0; ntp < 4; ntp++) {
            S[2*ntp][0] = S[2*ntp][1] = S[2*ntp][2] = S[2*ntp][3] = 0.0f;
            S[2*ntp+1][0] = S[2*ntp+1][1] = S[2*ntp+1][2] = S[2*ntp+1][3] = 0.0f;
            const unsigned* kp2 = Ks + ntp * 512 + lane * 4;
            #pragma unroll
            for (int kc = 0; kc < 4; kc++) {
                uint4 bb = *(const uint4*)(kp2 + kc * 128);
                mma_f16(S[2*ntp],   qf[kc][0], qf[kc][1], qf[kc][2], qf[kc][3], bb.x, bb.y);
                mma_f16(S[2*ntp+1], qf[kc][0], qf[kc][1], qf[kc][2], qf[kc][3], bb.z, bb.w);
            }
        }

        const bool full = (kbase + 63 <= qbase) && (kbase >= qbase - (WIN - 16));
        if (!full) {
            #pragma unroll
            for (int nt = 0; nt < 8; nt++) {
                const int j0 = kbase + nt * 8 + 2 * tig;
                const int j1 = j0 + 1;
                if (j0 > iA || j0 < iA - (WIN - 1)) S[nt][0] = NINF;
                if (j1 > iA || j1 < iA - (WIN - 1)) S[nt][1] = NINF;
                if (j0 > iB || j0 < iB - (WIN - 1)) S[nt][2] = NINF;
                if (j1 > iB || j1 < iB - (WIN - 1)) S[nt][3] = NINF;
            }
        }

        float mtA = NINF, mtB = NINF;
        #pragma unroll
        for (int nt = 0; nt < 8; nt++) {
            mtA = fmaxf(mtA, fmaxf(S[nt][0], S[nt][1]));
            mtB = fmaxf(mtB, fmaxf(S[nt][2], S[nt][3]));
        }
        mtA = fmaxf(mtA, __shfl_xor_sync(0xffffffffu, mtA, 1));
        mtA = fmaxf(mtA, __shfl_xor_sync(0xffffffffu, mtA, 2));
        mtB = fmaxf(mtB, __shfl_xor_sync(0xffffffffu, mtB, 1));
        mtB = fmaxf(mtB, __shfl_xor_sync(0xffffffffu, mtB, 2));

        const float mnA = fmaxf(mA, mtA);
        const float mnB = fmaxf(mB, mtB);
        const float corrA = __expf(mA - mnA);
        const float corrB = __expf(mB - mnB);

        float sumA = 0.0f, sumB = 0.0f;
        unsigned PbA[8], PbB[8];
        #pragma unroll
        for (int nt = 0; nt < 8; nt++) {
            float p0 = __expf(S[nt][0] - mnA);
            float p1 = __expf(S[nt][1] - mnA);
            float p2 = __expf(S[nt][2] - mnB);
            float p3 = __expf(S[nt][3] - mnB);
            unsigned ua = f2h2p(p0, p1);
            unsigned ub = f2h2p(p2, p3);
            PbA[nt] = ua; PbB[nt] = ub;
            float2 fa = __half22float2(*reinterpret_cast<__half2*>(&ua));
            float2 fb = __half22float2(*reinterpret_cast<__half2*>(&ub));
            sumA += fa.x + fa.y;
            sumB += fb.x + fb.y;
        }
        sumA += __shfl_xor_sync(0xffffffffu, sumA, 1);
        sumA += __shfl_xor_sync(0xffffffffu, sumA, 2);
        sumB += __shfl_xor_sync(0xffffffffu, sumB, 1);
        sumB += __shfl_xor_sync(0xffffffffu, sumB, 2);

        lA = lA * corrA + sumA;
        lB = lB * corrB + sumB;
        mA = mnA;
        mB = mnB;

        #pragma unroll
        for (int nt = 0; nt < 8; nt++) {
            Oa[nt][0] *= corrA;  Oa[nt][1] *= corrA;
            Oa[nt][2] *= corrB;  Oa[nt][3] *= corrB;
        }

        #pragma unroll
        for (int kc = 0; kc < 4; kc++) {
            const unsigned a0 = PbA[2 * kc];
            const unsigned a1 = PbB[2 * kc];
            const unsigned a2 = PbA[2 * kc + 1];
            const unsigned a3 = PbB[2 * kc + 1];
            const unsigned* vp2 = Vv + kc * 512 + lane * 4;
            #pragma unroll
            for (int nbp = 0; nbp < 4; nbp++) {
                uint4 bb = *(const uint4*)(vp2 + nbp * 128);
                mma_f16(Oa[2*nbp],   a0, a1, a2, a3, bb.x, bb.y);
                mma_f16(Oa[2*nbp+1], a0, a1, a2, a3, bb.z, bb.w);
            }
        }
    }

    {
        const float invA = 1.0f / lA;
        const float invB = 1.0f / lB;
        const int rb_g = b * 128 + qt * 8 + w;
        unsigned* basep = g_OPK + (size_t)rb_g * 8192;
        #pragma unroll
        for (int nt = 0; nt < 8; nt++) {
            const int kc_g = h * 4 + (nt >> 1);
            const size_t idx = ((size_t)kc_g * 32 + (g * 4 + tig)) * 4 + (nt & 1) * 2;
            basep[idx]     = f2h2p(Oa[nt][0] * invA, Oa[nt][1] * invA);
            basep[idx + 1] = f2h2p(Oa[nt][2] * invB, Oa[nt][3] * invB);
        }
    }
}

// ---------------------------------------------------------------------------
extern "C" void kernel_launch(void* const* d_in, const int* in_sizes, int n_in,
                              void* d_out, int out_size)
{
    const float* x  = (const float*)d_in[0];
    const float* Wq = (const float*)d_in[1];
    const float* bq = (const float*)d_in[2];
    const float* Wk = (const float*)d_in[3];
    const float* bk = (const float*)d_in[4];
    const float* Wv = (const float*)d_in[5];
    const float* bv = (const float*)d_in[6];
    const float* Wo = (const float*)d_in[7];
    const float* bo = (const float*)d_in[8];
    float* out = (float*)d_out;

    unsigned *xpk = nullptr, *wpk = nullptr;
    cudaGetSymbolAddress((void**)&xpk, g_XPK);
    cudaGetSymbolAddress((void**)&wpk, g_WPK);

    static bool attr_set = false;
    if (!attr_set) {
        cudaFuncSetAttribute(attn_kernel,
                             cudaFuncAttributeMaxDynamicSharedMemorySize,
                             ATT_SMEM_B);
        cudaFuncSetAttribute(qkv_gemm_kernel,
                             cudaFuncAttributeMaxDynamicSharedMemorySize,
                             GEMM_SMEM_B);
        cudaFuncSetAttribute(out_gemm_kernel,
                             cudaFuncAttributeMaxDynamicSharedMemorySize,
                             GEMM_SMEM_B);
        attr_set = true;
    }

    pack_all_kernel<<<dim3(2048, 2), 256>>>(x, Wq, Wk, Wv, Wo, xpk, wpk);

    dim3 gq(DM / 128, M_ROWS / 128, 3);
    qkv_gemm_kernel<<<gq, 256, GEMM_SMEM_B>>>(bq, bk, bv);

    const int nblk = B_SZ * HEADS * (T_SEQ / 128);  // 512
    attn_kernel<<<nblk, 256, ATT_SMEM_B>>>();

    dim3 go(DM / 128, M_ROWS / 128, 1);
    out_gemm_kernel<<<go, 256, GEMM_SMEM_B>>>(bo, out);
}